// round 7
// baseline (speedup 1.0000x reference)
#include <cuda_runtime.h>
#include <cstdint>

#define BB 2
#define DD 512
#define KK 32
#define NN 4096
#define NB 64
#define GRID 128
#define NTHR 1024
#define NCHOUT 32
#define ZSIZE (BB*DD*KK)

typedef unsigned long long ull;

// ---------- device scratch ----------
__device__ ulonglong2 g_ABp[DD*KK];      // {(s2,s2),(-2s2c,-2s2c)} 256KB
__device__ float g_C[KK];                // sum_d s^2 c^2
__device__ float g_S1part[GRID*KK];
__device__ float g_Mpart[NCHOUT][BB*DD*KK];
__device__ float g_SS[BB*64*KK];
__device__ unsigned g_sync[4];           // rotating barrier counters (zero-init)

// ---------- f32x2 helpers ----------
__device__ __forceinline__ ull pk2(float lo, float hi) {
    ull r; asm("mov.b64 %0, {%1,%2};" : "=l"(r) : "f"(lo), "f"(hi)); return r;
}
__device__ __forceinline__ void upk2(ull v, float& lo, float& hi) {
    asm("mov.b64 {%0,%1}, %2;" : "=f"(lo), "=f"(hi) : "l"(v));
}
__device__ __forceinline__ ull fma2(ull a, ull b, ull c) {
    ull d; asm("fma.rn.f32x2 %0, %1, %2, %3;" : "=l"(d) : "l"(a), "l"(b), "l"(c)); return d;
}

// ---------- grid barrier on counter i ----------
__device__ __forceinline__ void grid_sync_c(int i) {
    volatile unsigned* ctr = (volatile unsigned*)&g_sync[i];
    __syncthreads();
    if (threadIdx.x == 0) {
        __threadfence();
        atomicAdd(&g_sync[i], 1u);
        while (*ctr < GRID) { __nanosleep(32); }
        __threadfence();
    }
    __syncthreads();
}

// ---------- smem plan (192KB) ----------
// P1: Xs [512][64] @0 (128KB); AB0 @131072 (32KB); AB1 @163840 (32KB)
// P1 epilogue alias: Ep [32][1024] @0 (128KB); Ef [64][32] @131072; red @139264
// P2 alias: Xs2 [4][64][64] @0 (64KB); Qs2 [4][64][32] @65536 (32KB)
// P3/P4 alias: red @0; cwf @4224; bsh @5376
#define SMEM_TOTAL 196608

__global__ __launch_bounds__(NTHR) void fused_kernel(const float* __restrict__ X,
                                                     const float* __restrict__ cw,
                                                     const float* __restrict__ scale,
                                                     float* __restrict__ out) {
    extern __shared__ unsigned char sm[];
    const int tid  = threadIdx.x;
    const int lane = tid & 31;
    const int w    = tid >> 5;           // 0..31
    const int bid  = blockIdx.x;

    // ============ P0: packed coefficients + C[k] ============
    if (tid < 128) {
        int idx = bid*128 + tid;         // d*32+k
        int d = idx >> 5, k = idx & 31;
        float s = scale[idx];
        float c = cw[k*DD + d];
        float s2 = s*s;
        float bc = -2.f*s2*c;
        ulonglong2 v; v.x = pk2(s2, s2); v.y = pk2(bc, bc);
        g_ABp[idx] = v;
    }
    if (bid < KK) {
        float* red = (float*)sm;
        const int k = bid;
        float v = 0.f;
        if (tid < DD) {
            float s = scale[tid*KK + k];
            float c = cw[k*DD + tid];
            v = s*s*c*c;
        }
        red[tid] = v; __syncthreads();
        #pragma unroll
        for (int off = 512; off > 0; off >>= 1) {
            if (tid < off) red[tid] += red[tid + off];
            __syncthreads();
        }
        if (tid == 0) g_C[k] = red[0];
    }
    grid_sync_c(0);

    // ============ P1: E-GEMM + softmax -> Q ============
    {
        float*      Xs  = (float*)sm;                        // [512][64]
        ulonglong2* AB0 = (ulonglong2*)(sm + 131072);        // [2048]
        ulonglong2* AB1 = (ulonglong2*)(sm + 163840);

        const int ng = w >> 4;           // n-group 0/1 (32 n each)
        const int wd = w & 15;           // d slot
        const int n0 = bid * NB;
        const int b  = n0 >> 12;
        const float* Xb = X + (size_t)b*DD*NN + (n0 & (NN - 1));

        // stage all X once: [512][64]
        #pragma unroll
        for (int it = 0; it < 8; it++) {
            int idx = tid + it*1024;
            int r = idx >> 4, c4 = idx & 15;
            *(float4*)&Xs[r*64 + c4*4] = *(const float4*)(Xb + (size_t)r*NN + c4*4);
        }
        // stage AB chunk 0
        {
            const float4* src = (const float4*)g_ABp;
            float4* dst = (float4*)AB0;
            dst[tid] = src[tid];
            dst[tid + 1024] = src[tid + 1024];
        }
        __syncthreads();

        ull acc[16];
        #pragma unroll
        for (int i = 0; i < 16; i++) acc[i] = 0ull;

        #pragma unroll 1
        for (int c = 0; c < 8; c++) {
            const ulonglong2* ABcur = (c & 1) ? AB1 : AB0;
            ulonglong2*       ABnxt = (c & 1) ? AB0 : AB1;
            float4 p0, p1;
            if (c < 7) {
                const float4* src = (const float4*)(g_ABp + (c+1)*2048);
                p0 = src[tid]; p1 = src[tid + 1024];
            }
            #pragma unroll
            for (int it = 0; it < 4; it++) {
                int dd = wd + it*16;
                ulonglong2 abv = ABcur[dd*KK + lane];
                const float* xr = &Xs[(c*64 + dd)*64 + ng*32];
                #pragma unroll
                for (int g = 0; g < 8; g++) {
                    longlong2 xv = *reinterpret_cast<const longlong2*>(xr + g*4);
                    ull x01 = (ull)xv.x, x23 = (ull)xv.y;
                    ull t0 = fma2(abv.x, x01, abv.y);
                    acc[2*g]   = fma2(x01, t0, acc[2*g]);
                    ull t1 = fma2(abv.x, x23, abv.y);
                    acc[2*g+1] = fma2(x23, t1, acc[2*g+1]);
                }
            }
            if (c < 7) {
                float4* dst = (float4*)ABnxt;
                dst[tid] = p0; dst[tid + 1024] = p1;
            }
            __syncthreads();
        }

        // dump per-warp partials: acc[i] holds n_local (2i, 2i+1) for k=lane
        float* Ep  = (float*)sm;                 // [32][1024] aliases Xs (done)
        float* Ef  = (float*)(sm + 131072);      // [64][32]
        float* red = (float*)(sm + 139264);      // [32][33]
        #pragma unroll
        for (int i = 0; i < 16; i++) {
            float lo, hi; upk2(acc[i], lo, hi);
            Ep[w*1024 + (2*i  )*KK + lane] = lo;
            Ep[w*1024 + (2*i+1)*KK + lane] = hi;
        }
        __syncthreads();
        // reduce 16 d-slot warps per n-group
        #pragma unroll
        for (int it = 0; it < 2; it++) {
            int idx = tid + it*1024;             // n*32+k, n = 0..63
            int n = idx >> 5;
            int ngg = n >> 5;
            float s = 0.f;
            #pragma unroll
            for (int wdd = 0; wdd < 16; wdd++)
                s += Ep[(ngg*16 + wdd)*1024 + (n & 31)*KK + (idx & 31)];
            Ef[idx] = s;
        }
        __syncthreads();

        // softmax: warp w handles 2 n
        float* Qout = out + ZSIZE;
        const float Ck = g_C[lane];
        float s1loc = 0.f;
        #pragma unroll
        for (int i = 0; i < 2; i++) {
            int n = w*2 + i;
            float arg = -0.5f * (Ef[n*KK + lane] + Ck);
            float m = arg;
            #pragma unroll
            for (int off = 16; off; off >>= 1) m = fmaxf(m, __shfl_xor_sync(~0u, m, off));
            float ex = __expf(arg - m);
            float ssum = ex;
            #pragma unroll
            for (int off = 16; off; off >>= 1) ssum += __shfl_xor_sync(~0u, ssum, off);
            float q = ex / ssum;
            Qout[(size_t)(n0 + n)*KK + lane] = q;
            s1loc += q;
        }
        red[w*33 + lane] = s1loc;
        __syncthreads();
        if (w == 0) {
            float s = 0.f;
            #pragma unroll
            for (int i = 0; i < 32; i++) s += red[i*33 + lane];
            g_S1part[bid*KK + lane] = s;
        }
    }
    grid_sync_c(1);
    if (bid == 0 && tid == 0) {      // safe: all blocks passed sync0; no c3 arrival until sync2 completes
        atomicExch(&g_sync[0], 0u);
        atomicExch(&g_sync[3], 0u);
    }

    // ============ P2: Mpart[nc*4+grp][b,d,k] = sum_n Q*x ============
    {
        float* Xs2 = (float*)sm;             // [4][64][64]
        float* Qs2 = (float*)(sm + 65536);   // [4][64][32]
        const int b   = bid >> 6;
        const int dt  = (bid >> 3) & 7;
        const int nc  = bid & 7;
        const int grp = w >> 3;
        const int wg  = w & 7;
        const int d0  = dt*64;

        const float* Qb = out + ZSIZE + (size_t)b*NN*KK;
        const float* Xb = X + (size_t)b*DD*NN;

        ull acc2[8];
        #pragma unroll
        for (int j = 0; j < 8; j++) acc2[j] = 0ull;

        #pragma unroll 1
        for (int pass = 0; pass < 2; pass++) {
            #pragma unroll
            for (int it = 0; it < 4; it++) {
                int idx = tid + it*1024;
                int sl = idx >> 10, rr = (idx >> 4) & 63, cc = idx & 15;
                *(float4*)&Xs2[sl*4096 + rr*64 + cc*4] =
                    *(const float4*)(Xb + (size_t)(d0 + rr)*NN + nc*512 + (pass*4 + sl)*64 + cc*4);
            }
            #pragma unroll
            for (int it = 0; it < 2; it++) {
                int idx = tid + it*1024;
                int sl = idx >> 9, rem = idx & 511;
                *(float4*)&Qs2[sl*2048 + rem*4] =
                    *(const float4*)(Qb + ((size_t)(nc*512 + (pass*4 + sl)*64))*KK + rem*4);
            }
            __syncthreads();
            const float* Xt = &Xs2[grp*4096];
            const float* Qt = &Qs2[grp*2048];
            #pragma unroll
            for (int g = 0; g < 16; g++) {
                float q0 = Qt[(4*g+0)*KK + lane];
                float q1 = Qt[(4*g+1)*KK + lane];
                float q2 = Qt[(4*g+2)*KK + lane];
                float q3 = Qt[(4*g+3)*KK + lane];
                ull q01 = pk2(q0, q1), q23 = pk2(q2, q3);
                #pragma unroll
                for (int j = 0; j < 8; j++) {
                    longlong2 xv = *reinterpret_cast<const longlong2*>(&Xt[(wg*8+j)*64 + 4*g]);
                    acc2[j] = fma2(q01, (ull)xv.x, acc2[j]);
                    acc2[j] = fma2(q23, (ull)xv.y, acc2[j]);
                }
            }
            __syncthreads();
        }
        #pragma unroll
        for (int j = 0; j < 8; j++) {
            float lo, hi; upk2(acc2[j], lo, hi);
            g_Mpart[nc*4 + grp][((size_t)b*DD + d0 + wg*8 + j)*KK + lane] = lo + hi;
        }
    }
    grid_sync_c(2);
    if (bid == 0 && tid == 0) atomicExch(&g_sync[1], 0u);

    // ============ P3: unnormalized Z + sumsq partials ============
    const int bf  = bid >> 6;
    const int dtf = bid & 63;
    const int d0f = dtf*8;
    const int dfw = d0f + (w & 7);
    const size_t mi = ((size_t)bf*DD + dfw)*KK + lane;
    {
        float* red = (float*)sm;            // [32][33]
        float* cwf = (float*)(sm + 4224);   // [32][9]
        float* bsh = (float*)(sm + 5376);   // [32]

        if (tid < 256) {
            int k = tid >> 3, dl = tid & 7;
            cwf[k*9 + dl] = cw[k*DD + d0f + dl];
        }
        float s1p = g_S1part[(bf*64 + w)*KK + lane]
                  + g_S1part[(bf*64 + 32 + w)*KK + lane];
        red[w*33 + lane] = s1p;
        __syncthreads();
        if (w == 0) {
            float s = 0.f;
            #pragma unroll
            for (int i = 0; i < 32; i++) s += red[i*33 + lane];
            bsh[lane] = 1.f / s;
        }
        __syncthreads();
        float z = 0.f;
        if (w < 8) {
            float m = 0.f;
            #pragma unroll
            for (int c = 0; c < NCHOUT; c++) m += g_Mpart[c][mi];
            z = scale[dfw*KK + lane] * (m*bsh[lane] - cwf[lane*9 + (w & 7)]);
            out[mi] = z;
        }
        __syncthreads();
        if (w < 8) red[w*33 + lane] = z*z;
        __syncthreads();
        if (w == 0) {
            float s = 0.f;
            #pragma unroll
            for (int i = 0; i < 8; i++) s += red[i*33 + lane];
            g_SS[(bf*64 + dtf)*KK + lane] = s;
        }
    }
    grid_sync_c(3);
    if (bid == 0 && tid == 0) atomicExch(&g_sync[2], 0u);

    // ============ P4: rescale ============
    {
        float* red = (float*)sm;
        float* bsh = (float*)(sm + 5376);
        float ssp = g_SS[(bf*64 + w)*KK + lane]
                  + g_SS[(bf*64 + 32 + w)*KK + lane];
        red[w*33 + lane] = ssp;
        __syncthreads();
        if (w == 0) {
            float s = 0.f;
            #pragma unroll
            for (int i = 0; i < 32; i++) s += red[i*33 + lane];
            bsh[lane] = rsqrtf(s);
        }
        __syncthreads();
        if (w < 8) out[mi] *= bsh[lane];
    }
}

extern "C" void kernel_launch(void* const* d_in, const int* in_sizes, int n_in,
                              void* d_out, int out_size) {
    const float* X     = (const float*)d_in[0];
    const float* cw    = (const float*)d_in[1];
    const float* scale = (const float*)d_in[2];
    float* out = (float*)d_out;

    cudaFuncSetAttribute(fused_kernel, cudaFuncAttributeMaxDynamicSharedMemorySize,
                         SMEM_TOTAL);
    fused_kernel<<<GRID, NTHR, SMEM_TOTAL>>>(X, cw, scale, out);
}

// round 8
// speedup vs baseline: 1.1975x; 1.1975x over previous
#include <cuda_runtime.h>
#include <cstdint>

#define BB 2
#define DD 512
#define KK 32
#define NN 4096
#define NB 64
#define GRID 128
#define NTHR 1024
#define NCHOUT 32
#define ZSIZE (BB*DD*KK)

typedef unsigned long long ull;

// ---------- device scratch ----------
__device__ float g_Af[DD*KK];            // s^2
__device__ float g_Bf[DD*KK];            // -2 s^2 c
__device__ float g_C[KK];
__device__ float g_S1part[GRID*KK];
__device__ float g_Mpart[NCHOUT][BB*DD*KK];
__device__ float g_SS[BB*64*KK];
__device__ unsigned g_sync[4];           // rotating barrier counters (zero-init)

// ---------- f32x2 helpers ----------
__device__ __forceinline__ ull pk2(float lo, float hi) {
    ull r; asm("mov.b64 %0, {%1,%2};" : "=l"(r) : "f"(lo), "f"(hi)); return r;
}
__device__ __forceinline__ void upk2(ull v, float& lo, float& hi) {
    asm("mov.b64 {%0,%1}, %2;" : "=f"(lo), "=f"(hi) : "l"(v));
}
__device__ __forceinline__ ull fma2(ull a, ull b, ull c) {
    ull d; asm("fma.rn.f32x2 %0, %1, %2, %3;" : "=l"(d) : "l"(a), "l"(b), "l"(c)); return d;
}
__device__ __forceinline__ void gbar(int id) {
    asm volatile("bar.sync %0, %1;" :: "r"(id), "r"(256) : "memory");
}

// ---------- grid barrier on counter i (reset deferred; proven safe R7) ----------
__device__ __forceinline__ void grid_sync_c(int i) {
    volatile unsigned* ctr = (volatile unsigned*)&g_sync[i];
    __syncthreads();
    if (threadIdx.x == 0) {
        __threadfence();
        atomicAdd(&g_sync[i], 1u);
        while (*ctr < GRID) { __nanosleep(32); }
        __threadfence();
    }
    __syncthreads();
}

// ---------- smem plan (160KB) ----------
// P1: XG [4grp][2buf][64d][16n] 32KB @0 ; Asf 64KB @32768 ; Bsf 64KB @98304
// P1 epilogue alias (after block sync): Ep [32][512] 64KB @32768 ; Ef 8KB @98304 ; red @106496
// P2 alias: Xs2 [4][64][64] 64KB @0 ; Qs2 [4][64][32] 32KB @65536
// P3/P4 alias: red @0 ; cwf @4224 ; bsh @5376
#define OFF_ASF 32768
#define OFF_BSF 98304
#define OFF_EP  32768
#define OFF_EF  98304
#define OFF_RED 106496
#define SMEM_TOTAL 163840

__global__ __launch_bounds__(NTHR) void fused_kernel(const float* __restrict__ X,
                                                     const float* __restrict__ cw,
                                                     const float* __restrict__ scale,
                                                     float* __restrict__ out) {
    extern __shared__ unsigned char sm[];
    const int tid  = threadIdx.x;
    const int lane = tid & 31;
    const int w    = tid >> 5;           // 0..31
    const int grp  = w >> 3;             // 0..3
    const int wd   = w & 7;
    const int gt   = tid & 255;          // tid within group
    const int bid  = blockIdx.x;

    // ============ P0: coefficients + C[k] ============
    if (tid < 128) {
        int idx = bid*128 + tid;         // d*32+k
        int d = idx >> 5, k = idx & 31;
        float s = scale[idx];
        float c = cw[k*DD + d];
        g_Af[idx] = s*s;
        g_Bf[idx] = -2.f*s*s*c;
    }
    if (bid < KK) {
        float* red = (float*)sm;
        const int k = bid;
        float v = 0.f;
        if (tid < DD) {
            float s = scale[tid*KK + k];
            float c = cw[k*DD + tid];
            v = s*s*c*c;
        }
        red[tid] = v; __syncthreads();
        #pragma unroll
        for (int off = 512; off > 0; off >>= 1) {
            if (tid < off) red[tid] += red[tid + off];
            __syncthreads();
        }
        if (tid == 0) g_C[k] = red[0];
    }
    grid_sync_c(0);

    // ============ P1: E-GEMM + softmax -> Q (group-scoped pipeline) ============
    {
        float* XG  = (float*)sm;                    // [4][2][64][16]
        float* Asf = (float*)(sm + OFF_ASF);
        float* Bsf = (float*)(sm + OFF_BSF);

        const int n0 = bid * NB;
        const int b  = n0 >> 12;
        const float* Xb = X + (size_t)b*DD*NN + (n0 & (NN - 1)) + grp*16;
        float* XGg = XG + grp*2048;                 // this group's 2 buffers

        // stage all coefficients once (block-wide)
        #pragma unroll
        for (int it = 0; it < 4; it++) {
            ((float4*)Asf)[tid + it*1024] = ((const float4*)g_Af)[tid + it*1024];
            ((float4*)Bsf)[tid + it*1024] = ((const float4*)g_Bf)[tid + it*1024];
        }
        // preload own group's chunk 0: [64 d][16 n]
        const int sr = gt >> 2, sc = gt & 3;        // row 0..63, col-quad 0..3
        float4 xpre = *(const float4*)(Xb + (size_t)sr*NN + sc*4);
        *(float4*)&XGg[sr*16 + sc*4] = xpre;
        __syncthreads();                            // coeffs + chunk0 visible

        ull acc[8];
        #pragma unroll
        for (int i = 0; i < 8; i++) acc[i] = 0ull;

        #pragma unroll 1
        for (int c = 0; c < 8; c++) {
            const float* Xs = XGg + (c & 1)*1024;
            if (c < 7)
                xpre = *(const float4*)(Xb + (size_t)((c+1)*64 + sr)*NN + sc*4);
            const float* Ac = Asf + c*64*KK;
            const float* Bc = Bsf + c*64*KK;
            #pragma unroll
            for (int it = 0; it < 8; it++) {
                int dd = wd + it*8;
                float av = Ac[dd*KK + lane];
                float bv = Bc[dd*KK + lane];
                ull a2 = pk2(av, av), b2 = pk2(bv, bv);
                const float* xr = &Xs[dd*16];
                #pragma unroll
                for (int g = 0; g < 4; g++) {
                    longlong2 xv = *reinterpret_cast<const longlong2*>(xr + g*4);
                    ull x01 = (ull)xv.x, x23 = (ull)xv.y;
                    ull t0 = fma2(a2, x01, b2);
                    acc[2*g]   = fma2(x01, t0, acc[2*g]);
                    ull t1 = fma2(a2, x23, b2);
                    acc[2*g+1] = fma2(x23, t1, acc[2*g+1]);
                }
            }
            if (c < 7)
                *(float4*)&XGg[(1 - (c & 1))*1024 + sr*16 + sc*4] = xpre;
            gbar(1 + grp);
        }
        __syncthreads();                            // all groups done; safe to alias Asf

        // dump per-warp partials: Ep[w][16 nl][32 k]
        float* Ep  = (float*)(sm + OFF_EP);
        float* Ef  = (float*)(sm + OFF_EF);
        float* red = (float*)(sm + OFF_RED);
        #pragma unroll
        for (int i = 0; i < 8; i++) {
            float lo, hi; upk2(acc[i], lo, hi);
            Ep[w*512 + (2*i  )*KK + lane] = lo;
            Ep[w*512 + (2*i+1)*KK + lane] = hi;
        }
        __syncthreads();
        // Ef[n*32+k] = sum over the 8 d-slot warps of n's group
        #pragma unroll
        for (int it = 0; it < 2; it++) {
            int idx = tid + it*1024;                // n*32+k
            int n = idx >> 5, k = idx & 31;
            int gg = n >> 4, nl = n & 15;
            float s = 0.f;
            #pragma unroll
            for (int wdd = 0; wdd < 8; wdd++)
                s += Ep[(gg*8 + wdd)*512 + nl*KK + k];
            Ef[idx] = s;
        }
        __syncthreads();

        // softmax: warp w handles n = 2w, 2w+1
        float* Qout = out + ZSIZE;
        const float Ck = g_C[lane];
        float s1loc = 0.f;
        #pragma unroll
        for (int i = 0; i < 2; i++) {
            int n = w*2 + i;
            float arg = -0.5f * (Ef[n*KK + lane] + Ck);
            float m = arg;
            #pragma unroll
            for (int off = 16; off; off >>= 1) m = fmaxf(m, __shfl_xor_sync(~0u, m, off));
            float ex = __expf(arg - m);
            float ssum = ex;
            #pragma unroll
            for (int off = 16; off; off >>= 1) ssum += __shfl_xor_sync(~0u, ssum, off);
            float q = ex / ssum;
            Qout[(size_t)(n0 + n)*KK + lane] = q;
            s1loc += q;
        }
        red[w*33 + lane] = s1loc;
        __syncthreads();
        if (w == 0) {
            float s = 0.f;
            #pragma unroll
            for (int i = 0; i < 32; i++) s += red[i*33 + lane];
            g_S1part[bid*KK + lane] = s;
        }
    }
    grid_sync_c(1);
    if (bid == 0 && tid == 0) {      // safe: all blocks past sync0/sync1
        atomicExch(&g_sync[0], 0u);
        atomicExch(&g_sync[3], 0u);
    }

    // ============ P2: Mpart[nc*4+grp] = sum_n Q*x (group-scoped) ============
    {
        float* Xt = (float*)(sm + grp*16384);            // [64][64] own slice
        float* Qt = (float*)(sm + 65536 + grp*8192);     // [64][32] own slice
        const int b   = bid >> 6;
        const int dt  = (bid >> 3) & 7;
        const int nc  = bid & 7;
        const int wg  = wd;              // d rows wg*8..wg*8+7
        const int d0  = dt*64;

        const float* Qb = out + ZSIZE + (size_t)b*NN*KK;
        const float* Xb = X + (size_t)b*DD*NN;

        ull acc2[8];
        #pragma unroll
        for (int j = 0; j < 8; j++) acc2[j] = 0ull;

        #pragma unroll 1
        for (int pass = 0; pass < 2; pass++) {
            const int nbase = nc*512 + (pass*4 + grp)*64;
            // group stages its own X slice (1024 float4) and Q slice (512 float4)
            #pragma unroll
            for (int it = 0; it < 4; it++) {
                int idx = gt + it*256;
                int rr = idx >> 4, cc = idx & 15;
                *(float4*)&Xt[rr*64 + cc*4] =
                    *(const float4*)(Xb + (size_t)(d0 + rr)*NN + nbase + cc*4);
            }
            #pragma unroll
            for (int it = 0; it < 2; it++) {
                int idx = gt + it*256;
                *(float4*)&Qt[idx*4] = *(const float4*)(Qb + (size_t)nbase*KK + idx*4);
            }
            gbar(1 + grp);
            #pragma unroll
            for (int g = 0; g < 16; g++) {
                float q0 = Qt[(4*g+0)*KK + lane];
                float q1 = Qt[(4*g+1)*KK + lane];
                float q2 = Qt[(4*g+2)*KK + lane];
                float q3 = Qt[(4*g+3)*KK + lane];
                ull q01 = pk2(q0, q1), q23 = pk2(q2, q3);
                #pragma unroll
                for (int j = 0; j < 8; j++) {
                    longlong2 xv = *reinterpret_cast<const longlong2*>(&Xt[(wg*8+j)*64 + 4*g]);
                    acc2[j] = fma2(q01, (ull)xv.x, acc2[j]);
                    acc2[j] = fma2(q23, (ull)xv.y, acc2[j]);
                }
            }
            gbar(1 + grp);
        }
        #pragma unroll
        for (int j = 0; j < 8; j++) {
            float lo, hi; upk2(acc2[j], lo, hi);
            g_Mpart[nc*4 + grp][((size_t)b*DD + d0 + wg*8 + j)*KK + lane] = lo + hi;
        }
    }
    grid_sync_c(2);
    if (bid == 0 && tid == 0) atomicExch(&g_sync[1], 0u);

    // ============ P3: unnormalized Z + sumsq partials ============
    const int bf  = bid >> 6;
    const int dtf = bid & 63;
    const int d0f = dtf*8;
    const int dfw = d0f + (w & 7);
    const size_t mi = ((size_t)bf*DD + dfw)*KK + lane;
    {
        float* red = (float*)sm;            // [32][33]
        float* cwf = (float*)(sm + 4224);   // [32][9]
        float* bsh = (float*)(sm + 5376);   // [32]

        if (tid < 256) {
            int k = tid >> 3, dl = tid & 7;
            cwf[k*9 + dl] = cw[k*DD + d0f + dl];
        }
        float s1p = g_S1part[(bf*64 + w)*KK + lane]
                  + g_S1part[(bf*64 + 32 + w)*KK + lane];
        red[w*33 + lane] = s1p;
        __syncthreads();
        if (w == 0) {
            float s = 0.f;
            #pragma unroll
            for (int i = 0; i < 32; i++) s += red[i*33 + lane];
            bsh[lane] = 1.f / s;
        }
        __syncthreads();
        float z = 0.f;
        if (w < 8) {
            float m = 0.f;
            #pragma unroll
            for (int c = 0; c < NCHOUT; c++) m += g_Mpart[c][mi];
            z = scale[dfw*KK + lane] * (m*bsh[lane] - cwf[lane*9 + (w & 7)]);
            out[mi] = z;
        }
        __syncthreads();
        if (w < 8) red[w*33 + lane] = z*z;
        __syncthreads();
        if (w == 0) {
            float s = 0.f;
            #pragma unroll
            for (int i = 0; i < 8; i++) s += red[i*33 + lane];
            g_SS[(bf*64 + dtf)*KK + lane] = s;
        }
    }
    grid_sync_c(3);
    if (bid == 0 && tid == 0) atomicExch(&g_sync[2], 0u);

    // ============ P4: rescale ============
    {
        float* red = (float*)sm;
        float* bsh = (float*)(sm + 5376);
        float ssp = g_SS[(bf*64 + w)*KK + lane]
                  + g_SS[(bf*64 + 32 + w)*KK + lane];
        red[w*33 + lane] = ssp;
        __syncthreads();
        if (w == 0) {
            float s = 0.f;
            #pragma unroll
            for (int i = 0; i < 32; i++) s += red[i*33 + lane];
            bsh[lane] = rsqrtf(s);
        }
        __syncthreads();
        if (w < 8) out[mi] *= bsh[lane];
    }
}

extern "C" void kernel_launch(void* const* d_in, const int* in_sizes, int n_in,
                              void* d_out, int out_size) {
    const float* X     = (const float*)d_in[0];
    const float* cw    = (const float*)d_in[1];
    const float* scale = (const float*)d_in[2];
    float* out = (float*)d_out;

    cudaFuncSetAttribute(fused_kernel, cudaFuncAttributeMaxDynamicSharedMemorySize,
                         SMEM_TOTAL);
    fused_kernel<<<GRID, NTHR, SMEM_TOTAL>>>(X, cw, scale, out);
}

// round 9
// speedup vs baseline: 1.2068x; 1.0078x over previous
#include <cuda_runtime.h>
#include <cstdint>

#define BB 2
#define DD 512
#define KK 32
#define NN 4096
#define NB 64
#define GRID 128
#define NTHR 1024
#define ZSIZE (BB*DD*KK)

typedef unsigned long long ull;

// ---------- device scratch ----------
__device__ float g_Af[DD*KK];            // s^2
__device__ float g_Bf[DD*KK];            // -2 s^2 c
__device__ float g_C[KK];
__device__ float g_S1part[GRID*KK];
__device__ float g_M2[(size_t)BB*64*DD*KK];  // per-block M partials (8MB)
__device__ float g_SS[BB*64*KK];
__device__ unsigned g_sync[3];           // barrier counters (zero-init)

// ---------- f32x2 helpers ----------
__device__ __forceinline__ ull pk2(float lo, float hi) {
    ull r; asm("mov.b64 %0, {%1,%2};" : "=l"(r) : "f"(lo), "f"(hi)); return r;
}
__device__ __forceinline__ void upk2(ull v, float& lo, float& hi) {
    asm("mov.b64 {%0,%1}, %2;" : "=f"(lo), "=f"(hi) : "l"(v));
}
__device__ __forceinline__ ull fma2(ull a, ull b, ull c) {
    ull d; asm("fma.rn.f32x2 %0, %1, %2, %3;" : "=l"(d) : "l"(a), "l"(b), "l"(c)); return d;
}
__device__ __forceinline__ void gbar(int id) {
    asm volatile("bar.sync %0, %1;" :: "r"(id), "r"(256) : "memory");
}

__device__ __forceinline__ void grid_sync_c(int i) {
    volatile unsigned* ctr = (volatile unsigned*)&g_sync[i];
    __syncthreads();
    if (threadIdx.x == 0) {
        __threadfence();
        atomicAdd(&g_sync[i], 1u);
        while (*ctr < GRID) { __nanosleep(32); }
        __threadfence();
    }
    __syncthreads();
}

// ---------- smem plan ----------
// P1: XG [4grp][2buf][64d][16n] 32KB @0 ; Asf 64KB @32768 ; Bsf 64KB @98304
// P1 epilogue: Ep waves 32KB @0 (XG dead) ; Xs2 [512][64] 128KB @32768 (coeff dead, cp.async)
// Ef @163840 (8KB) ; Qs @172032 (8KB) ; red @180224
// P3/P4 alias @0: redM @0, redS @4224, cwf @8448, bsh @9600
#define OFF_ASF 32768
#define OFF_BSF 98304
#define OFF_XS2 32768
#define OFF_EF  163840
#define OFF_QS  172032
#define OFF_RED 180224
#define SMEM_TOTAL 184576

__global__ __launch_bounds__(NTHR) void fused_kernel(const float* __restrict__ X,
                                                     const float* __restrict__ cw,
                                                     const float* __restrict__ scale,
                                                     float* __restrict__ out) {
    extern __shared__ unsigned char sm[];
    const int tid  = threadIdx.x;
    const int lane = tid & 31;
    const int w    = tid >> 5;           // 0..31
    const int grp  = w >> 3;             // 0..3
    const int wd   = w & 7;
    const int gt   = tid & 255;
    const int bid  = blockIdx.x;

    uint32_t smem_u32;
    asm("{ .reg .u64 t; cvta.to.shared.u64 t, %1; cvt.u32.u64 %0, t; }"
        : "=r"(smem_u32) : "l"(sm));

    // ============ P0: coefficients + C[k] ============
    if (tid < 128) {
        int idx = bid*128 + tid;         // d*32+k
        int d = idx >> 5, k = idx & 31;
        float s = scale[idx];
        float c = cw[k*DD + d];
        g_Af[idx] = s*s;
        g_Bf[idx] = -2.f*s*s*c;
    }
    if (bid < KK) {
        float* red = (float*)sm;
        const int k = bid;
        float v = 0.f;
        if (tid < DD) {
            float s = scale[tid*KK + k];
            float c = cw[k*DD + tid];
            v = s*s*c*c;
        }
        red[tid] = v; __syncthreads();
        #pragma unroll
        for (int off = 512; off > 0; off >>= 1) {
            if (tid < off) red[tid] += red[tid + off];
            __syncthreads();
        }
        if (tid == 0) g_C[k] = red[0];
    }
    grid_sync_c(0);
    if (bid == 0 && tid == 0) atomicExch(&g_sync[2], 0u);  // clear stale (prev replay)

    const int n0 = bid * NB;
    const int b  = n0 >> 12;

    // ============ P1: E-GEMM (group-scoped pipeline) ============
    ull acc[8];
    {
        float* XG  = (float*)sm;                    // [4][2][64][16]
        float* Asf = (float*)(sm + OFF_ASF);
        float* Bsf = (float*)(sm + OFF_BSF);

        const float* Xb = X + (size_t)b*DD*NN + (n0 & (NN - 1)) + grp*16;
        float* XGg = XG + grp*2048;

        #pragma unroll
        for (int it = 0; it < 4; it++) {
            ((float4*)Asf)[tid + it*1024] = ((const float4*)g_Af)[tid + it*1024];
            ((float4*)Bsf)[tid + it*1024] = ((const float4*)g_Bf)[tid + it*1024];
        }
        const int sr = gt >> 2, sc = gt & 3;
        float4 xpre = *(const float4*)(Xb + (size_t)sr*NN + sc*4);
        *(float4*)&XGg[sr*16 + sc*4] = xpre;
        __syncthreads();

        #pragma unroll
        for (int i = 0; i < 8; i++) acc[i] = 0ull;

        #pragma unroll 1
        for (int c = 0; c < 8; c++) {
            const float* Xs = XGg + (c & 1)*1024;
            if (c < 7)
                xpre = *(const float4*)(Xb + (size_t)((c+1)*64 + sr)*NN + sc*4);
            const float* Ac = Asf + c*64*KK;
            const float* Bc = Bsf + c*64*KK;
            #pragma unroll
            for (int it = 0; it < 8; it++) {
                int dd = wd + it*8;
                float av = Ac[dd*KK + lane];
                float bv = Bc[dd*KK + lane];
                ull a2 = pk2(av, av), b2 = pk2(bv, bv);
                const float* xr = &Xs[dd*16];
                #pragma unroll
                for (int g = 0; g < 4; g++) {
                    longlong2 xv = *reinterpret_cast<const longlong2*>(xr + g*4);
                    ull x01 = (ull)xv.x, x23 = (ull)xv.y;
                    ull t0 = fma2(a2, x01, b2);
                    acc[2*g]   = fma2(x01, t0, acc[2*g]);
                    ull t1 = fma2(a2, x23, b2);
                    acc[2*g+1] = fma2(x23, t1, acc[2*g+1]);
                }
            }
            if (c < 7)
                *(float4*)&XGg[(1 - (c & 1))*1024 + sr*16 + sc*4] = xpre;
            gbar(1 + grp);
        }
        __syncthreads();        // all groups done; XG + coeff regions now dead
    }

    // ---- kick off X re-stage [512 d][64 n] via cp.async (overlaps epilogue) ----
    {
        const float* Xb2 = X + (size_t)b*DD*NN + (n0 & (NN - 1));
        #pragma unroll
        for (int it = 0; it < 8; it++) {
            int idx = tid + it*1024;     // 0..8191 float4
            int row = idx >> 4, c4 = idx & 15;
            uint32_t dst = smem_u32 + OFF_XS2 + (uint32_t)(row*64 + c4*4)*4u;
            const float* src = Xb2 + (size_t)row*NN + c4*4;
            asm volatile("cp.async.ca.shared.global [%0], [%1], 16;"
                         :: "r"(dst), "l"(src));
        }
        asm volatile("cp.async.commit_group;");
    }

    // ---- E cross-warp reduce in two 32KB waves @0, then softmax ----
    {
        float* Ep  = (float*)sm;                 // [16][512] wave buffer
        float* Ef  = (float*)(sm + OFF_EF);      // [64][32]
        float* Qs  = (float*)(sm + OFF_QS);      // [64][32]
        float* red = (float*)(sm + OFF_RED);     // [32][33]

        if (w < 16) {
            #pragma unroll
            for (int i = 0; i < 8; i++) {
                float lo, hi; upk2(acc[i], lo, hi);
                Ep[w*512 + (2*i  )*KK + lane] = lo;
                Ep[w*512 + (2*i+1)*KK + lane] = hi;
            }
        }
        __syncthreads();
        {   // wave A: n 0..31 (groups 0,1 = warps 0..15)
            int n = tid >> 5, k = tid & 31;
            int gg = n >> 4, nl = n & 15;
            float s = 0.f;
            #pragma unroll
            for (int wdd = 0; wdd < 8; wdd++)
                s += Ep[(gg*8 + wdd)*512 + nl*KK + k];
            Ef[n*KK + k] = s;
        }
        __syncthreads();
        if (w >= 16) {
            #pragma unroll
            for (int i = 0; i < 8; i++) {
                float lo, hi; upk2(acc[i], lo, hi);
                Ep[(w-16)*512 + (2*i  )*KK + lane] = lo;
                Ep[(w-16)*512 + (2*i+1)*KK + lane] = hi;
            }
        }
        __syncthreads();
        {   // wave B: n 32..63
            int n = tid >> 5, k = tid & 31;
            int gg = n >> 4, nl = n & 15;
            float s = 0.f;
            #pragma unroll
            for (int wdd = 0; wdd < 8; wdd++)
                s += Ep[(gg*8 + wdd)*512 + nl*KK + k];
            Ef[(32 + n)*KK + k] = s;
        }
        __syncthreads();

        // softmax: warp w handles n = 2w, 2w+1 ; write Q to global AND smem
        float* Qout = out + ZSIZE;
        const float Ck = g_C[lane];
        float s1loc = 0.f;
        #pragma unroll
        for (int i = 0; i < 2; i++) {
            int n = w*2 + i;
            float arg = -0.5f * (Ef[n*KK + lane] + Ck);
            float m = arg;
            #pragma unroll
            for (int off = 16; off; off >>= 1) m = fmaxf(m, __shfl_xor_sync(~0u, m, off));
            float ex = __expf(arg - m);
            float ssum = ex;
            #pragma unroll
            for (int off = 16; off; off >>= 1) ssum += __shfl_xor_sync(~0u, ssum, off);
            float q = ex / ssum;
            Qout[(size_t)(n0 + n)*KK + lane] = q;
            Qs[n*KK + lane] = q;
            s1loc += q;
        }
        red[w*33 + lane] = s1loc;
        __syncthreads();
        if (w == 0) {
            float s = 0.f;
            #pragma unroll
            for (int i = 0; i < 32; i++) s += red[i*33 + lane];
            g_S1part[bid*KK + lane] = s;
        }
    }
    asm volatile("cp.async.wait_group 0;");
    __syncthreads();             // Xs2 + Qs visible to all

    // ============ P2': M partial over this block's 64 n, ALL 512 d ============
    {
        const float* Xs2 = (const float*)(sm + OFF_XS2);   // [512][64]
        const float* Qs  = (const float*)(sm + OFF_QS);    // [64][32]
        const int chunk = bid & 63;
        const int dbase = w*16;

        ull acc2[16];
        #pragma unroll
        for (int i = 0; i < 16; i++) acc2[i] = 0ull;

        #pragma unroll 1
        for (int ng = 0; ng < 4; ng++) {
            ull q2[8];
            #pragma unroll
            for (int j = 0; j < 8; j++)
                q2[j] = pk2(Qs[(ng*16 + 2*j)*KK + lane],
                            Qs[(ng*16 + 2*j + 1)*KK + lane]);
            #pragma unroll
            for (int dl = 0; dl < 16; dl++) {
                const float* xr = &Xs2[(dbase + dl)*64 + ng*16];
                longlong2 xa = *(const longlong2*)(xr);
                longlong2 xb = *(const longlong2*)(xr + 4);
                longlong2 xc = *(const longlong2*)(xr + 8);
                longlong2 xd = *(const longlong2*)(xr + 12);
                ull a = acc2[dl];
                a = fma2(q2[0], (ull)xa.x, a);
                a = fma2(q2[1], (ull)xa.y, a);
                a = fma2(q2[2], (ull)xb.x, a);
                a = fma2(q2[3], (ull)xb.y, a);
                a = fma2(q2[4], (ull)xc.x, a);
                a = fma2(q2[5], (ull)xc.y, a);
                a = fma2(q2[6], (ull)xd.x, a);
                a = fma2(q2[7], (ull)xd.y, a);
                acc2[dl] = a;
            }
        }
        float* dst = g_M2 + ((size_t)b*64 + chunk)*DD*KK;
        #pragma unroll
        for (int dl = 0; dl < 16; dl++) {
            float lo, hi; upk2(acc2[dl], lo, hi);
            dst[(dbase + dl)*KK + lane] = lo + hi;
        }
    }
    grid_sync_c(1);
    if (bid == 0 && tid == 0) atomicExch(&g_sync[0], 0u);

    // ============ P3: reduce 64 chunks, S1, Z, sumsq ============
    const int bf  = bid >> 6;
    const int dtf = bid & 63;
    const int d0f = dtf*8;
    const int dfw = d0f + (w & 7);
    const size_t mi = ((size_t)bf*DD + dfw)*KK + lane;
    {
        float* redM = (float*)sm;            // [32][33]
        float* redS = (float*)(sm + 4224);   // [32][33]
        float* cwf  = (float*)(sm + 8448);   // [32][9]
        float* bsh  = (float*)(sm + 9600);   // [32]
        const int wd8 = w & 7, cg = w >> 3;

        // chunk-partial: warp sums 16 of 64 chunks for d = d0f + wd8
        float mp = 0.f;
        const float* msrc = g_M2 + (size_t)bf*64*DD*KK + (size_t)(d0f + wd8)*KK + lane;
        #pragma unroll
        for (int j = 0; j < 16; j++)
            mp += msrc[(size_t)(cg*16 + j)*DD*KK];
        redM[w*33 + lane] = mp;

        float s1p = g_S1part[(bf*64 + w)*KK + lane]
                  + g_S1part[(bf*64 + 32 + w)*KK + lane];
        redS[w*33 + lane] = s1p;
        if (tid < 256) {
            int k = tid >> 3, dl = tid & 7;
            cwf[k*9 + dl] = cw[k*DD + d0f + dl];
        }
        __syncthreads();
        if (w == 0) {
            float s = 0.f;
            #pragma unroll
            for (int i = 0; i < 32; i++) s += redS[i*33 + lane];
            bsh[lane] = 1.f / s;
        }
        __syncthreads();
        float z = 0.f;
        if (w < 8) {
            float m = redM[w*33 + lane] + redM[(8+w)*33 + lane]
                    + redM[(16+w)*33 + lane] + redM[(24+w)*33 + lane];
            z = scale[dfw*KK + lane] * (m*bsh[lane] - cwf[lane*9 + w]);
            out[mi] = z;
        }
        __syncthreads();
        if (w < 8) redM[w*33 + lane] = z*z;
        __syncthreads();
        if (w == 0) {
            float s = 0.f;
            #pragma unroll
            for (int i = 0; i < 8; i++) s += redM[i*33 + lane];
            g_SS[(bf*64 + dtf)*KK + lane] = s;
        }
    }
    grid_sync_c(2);
    if (bid == 0 && tid == 0) atomicExch(&g_sync[1], 0u);

    // ============ P4: rescale ============
    {
        float* red = (float*)sm;
        float* bsh = (float*)(sm + 9600);
        float ssp = g_SS[(bf*64 + w)*KK + lane]
                  + g_SS[(bf*64 + 32 + w)*KK + lane];
        red[w*33 + lane] = ssp;
        __syncthreads();
        if (w == 0) {
            float s = 0.f;
            #pragma unroll
            for (int i = 0; i < 32; i++) s += red[i*33 + lane];
            bsh[lane] = rsqrtf(s);
        }
        __syncthreads();
        if (w < 8) out[mi] *= bsh[lane];
    }
}

extern "C" void kernel_launch(void* const* d_in, const int* in_sizes, int n_in,
                              void* d_out, int out_size) {
    const float* X     = (const float*)d_in[0];
    const float* cw    = (const float*)d_in[1];
    const float* scale = (const float*)d_in[2];
    float* out = (float*)d_out;

    cudaFuncSetAttribute(fused_kernel, cudaFuncAttributeMaxDynamicSharedMemorySize,
                         SMEM_TOTAL);
    fused_kernel<<<GRID, NTHR, SMEM_TOTAL>>>(X, cw, scale, out);
}